// round 4
// baseline (speedup 1.0000x reference)
#include <cuda_runtime.h>
#include <math.h>

#define BB 8
#define NN 128
#define CC 128
#define PAD 132

// ---- scratch (no allocations allowed) ----
__device__ float g_ep[BB*NN*NN];
__device__ float g_vpA[BB*NN*CC];
__device__ float g_vpB[BB*NN*CC];
__device__ float g_q[BB*NN*CC];
__device__ float g_k[BB*NN*CC];
__device__ float g_attn[BB*NN*NN];

__device__ __forceinline__ float lrelu(float x) { return x >= 0.f ? x : 0.01f * x; }

#define BN_SCALE 0.9999950000374997f

// generic block reductions (all threads must call; contribute 0 / -inf when inactive)
__device__ __forceinline__ float blockReduceSum(float v, float* red) {
    int tid = threadIdx.x;
    int nw = blockDim.x >> 5;
    #pragma unroll
    for (int off = 16; off; off >>= 1) v += __shfl_down_sync(0xffffffffu, v, off);
    if ((tid & 31) == 0) red[tid >> 5] = v;
    __syncthreads();
    float s = (tid < nw) ? red[tid] : 0.f;
    if (tid < 32) {
        #pragma unroll
        for (int off = 16; off; off >>= 1) s += __shfl_down_sync(0xffffffffu, s, off);
        if (tid == 0) red[0] = s;
    }
    __syncthreads();
    float r = red[0];
    __syncthreads();
    return r;
}

__device__ __forceinline__ float blockReduceMax(float v, float* red) {
    int tid = threadIdx.x;
    int nw = blockDim.x >> 5;
    #pragma unroll
    for (int off = 16; off; off >>= 1) v = fmaxf(v, __shfl_down_sync(0xffffffffu, v, off));
    if ((tid & 31) == 0) red[tid >> 5] = v;
    __syncthreads();
    float s = (tid < nw) ? red[tid] : -1e30f;
    if (tid < 32) {
        #pragma unroll
        for (int off = 16; off; off >>= 1) s = fmaxf(s, __shfl_down_sync(0xffffffffu, s, off));
        if (tid == 0) red[0] = s;
    }
    __syncthreads();
    float r = red[0];
    __syncthreads();
    return r;
}

// ============================================================================
// psim: fused (sim -> MLP -> sigmoid -> mask/topk -> l1norm -> renorm) per (b,i)
// block = 256 threads, grid = B*N
// ============================================================================
__global__ void psim_kernel(const float* __restrict__ vp, const float* __restrict__ ep_in,
                            float* __restrict__ ep_out,
                            const float* __restrict__ w1, const float* __restrict__ w2,
                            const float* __restrict__ w3, const float* __restrict__ b3,
                            int kval)
{
    extern __shared__ float sm[];
    float* S   = sm;                  // [CC][PAD]  sim transposed: S[c*PAD + j]; reused later as H2[j][PAD]
    float* H1T = S + CC * PAD;        // [2*CC][PAD] : H1T[o*PAD + j]
    float* Wt  = H1T + 2 * CC * PAD;  // [16][PAD]
    float* vpi = Wt + 16 * PAD;       // [128]
    float* w3s = vpi + NN;            // [128]
    float* ev  = w3s + NN;            // [128]
    float* red = ev + NN;             // [32]

    const int tid = threadIdx.x;
    const int b = blockIdx.x >> 7;
    const int i = blockIdx.x & 127;
    const float* vpb = vp + b * NN * CC;

    if (tid < NN) { vpi[tid] = vpb[i * CC + tid]; w3s[tid] = w3[tid]; }
    __syncthreads();

    // build sim transposed: S[c][j] = (vp[i,c] - vp[j,c])^2
    for (int idx = tid; idx < NN * CC; idx += 256) {
        int j = idx >> 7, c = idx & 127;
        float d = vpi[c] - vpb[j * CC + c];
        S[c * PAD + j] = d * d;
    }

    const int ty = tid >> 4, tx = tid & 15;
    const int r0 = ty * 8, o0 = tx * 8;

    // ---- GEMM1: H1[j][o] = lrelu(bn( sum_c S[j][c] * w1[c][o] )), o in [0,256) ----
    for (int oh = 0; oh < 2; ++oh) {
        float acc[8][8];
        #pragma unroll
        for (int x = 0; x < 8; ++x)
            #pragma unroll
            for (int y = 0; y < 8; ++y) acc[x][y] = 0.f;

        for (int k0 = 0; k0 < CC; k0 += 16) {
            __syncthreads();
            for (int idx = tid; idx < 16 * 128; idx += 256) {
                int c = idx >> 7, o = idx & 127;
                Wt[c * PAD + o] = w1[(k0 + c) * 256 + oh * 128 + o];
            }
            __syncthreads();
            #pragma unroll
            for (int c = 0; c < 16; ++c) {
                float4 a0 = *reinterpret_cast<const float4*>(&S[(k0 + c) * PAD + r0]);
                float4 a1 = *reinterpret_cast<const float4*>(&S[(k0 + c) * PAD + r0 + 4]);
                float4 b0 = *reinterpret_cast<const float4*>(&Wt[c * PAD + o0]);
                float4 b1 = *reinterpret_cast<const float4*>(&Wt[c * PAD + o0 + 4]);
                float a_[8] = {a0.x, a0.y, a0.z, a0.w, a1.x, a1.y, a1.z, a1.w};
                float b_[8] = {b0.x, b0.y, b0.z, b0.w, b1.x, b1.y, b1.z, b1.w};
                #pragma unroll
                for (int x = 0; x < 8; ++x)
                    #pragma unroll
                    for (int y = 0; y < 8; ++y)
                        acc[x][y] += a_[x] * b_[y];
            }
        }
        #pragma unroll
        for (int x = 0; x < 8; ++x)
            #pragma unroll
            for (int y = 0; y < 8; ++y)
                H1T[(oh * 128 + o0 + y) * PAD + r0 + x] = lrelu(acc[x][y] * BN_SCALE);
    }

    // ---- GEMM2: H2[j][o] = lrelu(bn( sum_k H1[j][k] * w2[k][o] )) ----
    float acc2[8][8];
    #pragma unroll
    for (int x = 0; x < 8; ++x)
        #pragma unroll
        for (int y = 0; y < 8; ++y) acc2[x][y] = 0.f;

    for (int k0 = 0; k0 < 256; k0 += 16) {
        __syncthreads();
        for (int idx = tid; idx < 16 * 128; idx += 256) {
            int c = idx >> 7, o = idx & 127;
            Wt[c * PAD + o] = w2[(k0 + c) * 128 + o];
        }
        __syncthreads();
        #pragma unroll
        for (int c = 0; c < 16; ++c) {
            float4 a0 = *reinterpret_cast<const float4*>(&H1T[(k0 + c) * PAD + r0]);
            float4 a1 = *reinterpret_cast<const float4*>(&H1T[(k0 + c) * PAD + r0 + 4]);
            float4 b0 = *reinterpret_cast<const float4*>(&Wt[c * PAD + o0]);
            float4 b1 = *reinterpret_cast<const float4*>(&Wt[c * PAD + o0 + 4]);
            float a_[8] = {a0.x, a0.y, a0.z, a0.w, a1.x, a1.y, a1.z, a1.w};
            float b_[8] = {b0.x, b0.y, b0.z, b0.w, b1.x, b1.y, b1.z, b1.w};
            #pragma unroll
            for (int x = 0; x < 8; ++x)
                #pragma unroll
                for (int y = 0; y < 8; ++y)
                    acc2[x][y] += a_[x] * b_[y];
        }
    }
    // write H2 (reuse S region) as [j][PAD]
    #pragma unroll
    for (int x = 0; x < 8; ++x)
        #pragma unroll
        for (int y = 0; y < 8; ++y)
            S[(r0 + x) * PAD + o0 + y] = lrelu(acc2[x][y] * BN_SCALE);
    __syncthreads();

    // ---- e_j = sigmoid(H2[j] . w3 + b3) ----
    float e = 0.f;
    if (tid < NN) {
        const float* h2row = S + tid * PAD;
        #pragma unroll 4
        for (int o = 0; o < 128; ++o) e += h2row[o] * w3s[o];
        e += b3[0];
        e = 1.f / (1.f + expf(-e));
    }

    // ---- postprocess row with ep ----
    float eplv = 0.f;
    if (tid < NN) {
        float epv = ep_in[(b * NN + i) * NN + tid];
        eplv = (tid == i) ? 0.f : epv;
    }
    float em = e * eplv;
    if (tid < NN) ev[tid] = em;
    float ep_sum = blockReduceSum(eplv, red);   // also orders ev[] writes

    if (kval > 0 && kval < NN) {
        int cnt = 0;
        float mine = 0.f;
        if (tid < NN) {
            mine = ev[tid];
            for (int j = 0; j < NN; ++j) {
                float o = ev[j];
                cnt += (o > mine) || (o == mine && j < tid);
            }
        }
        if (tid < NN && cnt >= kval) em = 0.f;
    }

    float s = blockReduceSum(fabsf(em), red);
    float scale = ep_sum / fmaxf(s, 1e-12f);
    float val = 0.f;
    if (tid < NN) val = em * scale + ((tid == i) ? 1.f : 0.f) + 1e-6f;
    float rowsum = blockReduceSum(val, red);
    if (tid < NN) ep_out[(b * NN + i) * NN + tid] = val / rowsum;
}

// ============================================================================
// q/k projection: block per (b,n), 256 threads (128 for q, 128 for k)
// ============================================================================
__global__ void proj_kernel(const float* __restrict__ vp, const float* __restrict__ wq,
                            const float* __restrict__ wk,
                            float* __restrict__ q, float* __restrict__ k)
{
    __shared__ float row[128];
    int tid = threadIdx.x;
    int bn = blockIdx.x;
    if (tid < 128) row[tid] = vp[bn * CC + tid];
    __syncthreads();
    int o = tid & 127;
    const float* w = (tid < 128) ? wq : wk;
    float acc = 0.f;
    #pragma unroll 4
    for (int c = 0; c < 128; ++c) acc += row[c] * w[c * 128 + o];
    if (tid < 128) q[bn * 128 + o] = acc;
    else           k[bn * 128 + o] = acc;
}

// ============================================================================
// mha: attn[b,i,j] = mean_h softmax_j(q_i . k_j / sqrt(dk)); block per (b,i), 128 thr
// ============================================================================
__global__ void mha_kernel(const float* __restrict__ q, const float* __restrict__ k,
                           float* __restrict__ attn)
{
    extern __shared__ float sm[];
    float* kb   = sm;               // [128][129]
    float* qrow = kb + 128 * 129;   // [128]
    float* red  = qrow + 128;       // [32]
    int tid = threadIdx.x;          // 128
    int b = blockIdx.x >> 7, i = blockIdx.x & 127;
    const float* ksrc = k + b * NN * CC;
    for (int idx = tid; idx < NN * CC; idx += 128) {
        int j = idx >> 7, c = idx & 127;
        kb[j * 129 + c] = ksrc[idx];
    }
    qrow[tid] = q[(b * NN + i) * CC + tid];
    __syncthreads();

    const float isd = 0.17677669529663687f; // 1/sqrt(32)
    float out = 0.f;
    for (int h = 0; h < 4; ++h) {
        float l = 0.f;
        const float* kr = kb + tid * 129 + h * 32;
        const float* qr = qrow + h * 32;
        #pragma unroll
        for (int d = 0; d < 32; ++d) l += qr[d] * kr[d];
        l *= isd;
        float mx = blockReduceMax(l, red);
        float ex = expf(l - mx);
        float ssum = blockReduceSum(ex, red);
        out += ex / ssum;
    }
    attn[(b * NN + i) * NN + tid] = out * 0.25f;
}

// ============================================================================
// d2p: vp_new = mlp(cat(vp_i, l1norm(masked ep*attn) @ vp)); block per (b,i), 256 thr
// ============================================================================
__global__ void d2p_kernel(const float* __restrict__ ep, const float* __restrict__ attn,
                           const float* __restrict__ vp, float* __restrict__ vp_out,
                           const float* __restrict__ w1, const float* __restrict__ w2)
{
    __shared__ float edge[128];
    __shared__ float nf[256];
    __shared__ float h[256];
    __shared__ float red[32];
    int tid = threadIdx.x;  // 256
    int b = blockIdx.x >> 7, i = blockIdx.x & 127;
    const float* vpb = vp + b * NN * CC;

    float wv = 0.f;
    if (tid < 128) {
        wv = ep[(b * NN + i) * NN + tid] * attn[(b * NN + i) * NN + tid];
        if (tid == i) wv = 0.f;
    }
    float s = blockReduceSum(fabsf(wv), red);
    float inv = 1.f / fmaxf(s, 1e-12f);
    if (tid < 128) { edge[tid] = wv * inv; nf[tid] = vpb[i * CC + tid]; }
    __syncthreads();
    if (tid >= 128) {
        int c = tid - 128;
        float a = 0.f;
        #pragma unroll 4
        for (int j = 0; j < 128; ++j) a += edge[j] * vpb[j * CC + c];
        nf[128 + c] = a;
    }
    __syncthreads();
    {
        float acc = 0.f;
        #pragma unroll 4
        for (int kk = 0; kk < 256; ++kk) acc += nf[kk] * w1[kk * 256 + tid];
        h[tid] = lrelu(acc * BN_SCALE);
    }
    __syncthreads();
    if (tid < 128) {
        float acc = 0.f;
        #pragma unroll 4
        for (int kk = 0; kk < 256; ++kk) acc += h[kk] * w2[kk * 128 + tid];
        vp_out[(b * NN + i) * CC + tid] = lrelu(acc * BN_SCALE);
    }
}

// ============================================================================
extern "C" void kernel_launch(void* const* d_in, const int* in_sizes, int n_in,
                              void* d_out, int out_size)
{
    const float* vp      = (const float*)d_in[0];
    const float* ep0     = (const float*)d_in[1];
    const float* pre_w1  = (const float*)d_in[2];
    const float* pre_w2  = (const float*)d_in[3];
    const float* pre_w3  = (const float*)d_in[4];
    const float* pre_b3  = (const float*)d_in[5];
    const float* ps_w1   = (const float*)d_in[6];
    const float* ps_w2   = (const float*)d_in[7];
    const float* ps_w3   = (const float*)d_in[8];
    const float* ps_b3   = (const float*)d_in[9];
    const float* d2pw1   = (const float*)d_in[10];
    const float* d2pw2   = (const float*)d_in[11];
    const float* mha_wq  = (const float*)d_in[12];
    const float* mha_wk  = (const float*)d_in[13];
    float* out = (float*)d_out;

    float *ep, *vpA, *vpB, *qb, *kb, *at;
    cudaGetSymbolAddress((void**)&ep,  g_ep);
    cudaGetSymbolAddress((void**)&vpA, g_vpA);
    cudaGetSymbolAddress((void**)&vpB, g_vpB);
    cudaGetSymbolAddress((void**)&qb,  g_q);
    cudaGetSymbolAddress((void**)&kb,  g_k);
    cudaGetSymbolAddress((void**)&at,  g_attn);

    const int psim_smem = (CC * PAD + 2 * CC * PAD + 16 * PAD + 3 * NN + 32) * (int)sizeof(float);
    cudaFuncSetAttribute(psim_kernel, cudaFuncAttributeMaxDynamicSharedMemorySize, psim_smem);
    const int mha_smem = (128 * 129 + 128 + 32) * (int)sizeof(float);
    cudaFuncSetAttribute(mha_kernel, cudaFuncAttributeMaxDynamicSharedMemorySize, mha_smem);

    dim3 grid(BB * NN);

    // ep = psim_pre(vp, ep0), no top-k
    psim_kernel<<<grid, 256, psim_smem>>>(vp, ep0, ep, pre_w1, pre_w2, pre_w3, pre_b3, -1);

    const float* vcur = vp;
    float* vbuf[2] = {vpA, vpB};
    for (int g = 0; g < 2; ++g) {
        proj_kernel<<<grid, 256>>>(vcur, mha_wq + g * 128 * 128, mha_wk + g * 128 * 128, qb, kb);
        mha_kernel<<<grid, 128, mha_smem>>>(qb, kb, at);
        d2p_kernel<<<grid, 256>>>(ep, at, vcur, vbuf[g],
                                  d2pw1 + g * 256 * 256, d2pw2 + g * 256 * 128);
        int kv = (g == 0) ? 115 : 102;  // int(128*(1-0.1*(g+1)))
        float* epo = (g == 1) ? out : ep;
        psim_kernel<<<grid, 256, psim_smem>>>(vbuf[g], ep, epo,
                                              ps_w1 + g * 128 * 256, ps_w2 + g * 256 * 128,
                                              ps_w3 + g * 128, ps_b3 + g, kv);
        vcur = vbuf[g];
    }
}